// round 1
// baseline (speedup 1.0000x reference)
#include <cuda_runtime.h>
#include <math.h>
#include <float.h>

// Problem constants
#define B 8
#define S 512
#define H 768
#define NTOT (B*S*H)   // 3145728

// Gate state + scratch (no cudaMalloc allowed)
__device__ int   g_index;
__device__ float g_w;
__device__ __align__(16) float g_y[NTOT];    // conv output, layout [B][O][S]
__device__ __align__(16) float g_dw[NTOT];   // depthwise intermediate, layout [B][C][S]
__device__ float g_mean[H];
__device__ float g_var[H];

// ---------------------------------------------------------------------------
// Gate: gumbel straight-through. Single thread (10 elements).
// ---------------------------------------------------------------------------
__global__ void gate_k(const float* __restrict__ u, const float* __restrict__ arch)
{
    if (threadIdx.x != 0) return;
    float a[10], lg[10], p[10];
    float m = -FLT_MAX;
    for (int i = 0; i < 10; i++) { a[i] = arch[i]; m = fmaxf(m, a[i]); }
    float se = 0.f;
    for (int i = 0; i < 10; i++) se += expf(a[i] - m);
    float lse = m + logf(se);
    float m2 = -FLT_MAX;
    for (int i = 0; i < 10; i++) {
        float uc = fminf(fmaxf(u[i], 1e-9f), 1.f - 1e-9f);
        float gum = -logf(-logf(uc));
        lg[i] = ((a[i] - lse) + gum) * (1.f / 10.f);
        m2 = fmaxf(m2, lg[i]);
    }
    float s2 = 0.f;
    for (int i = 0; i < 10; i++) { p[i] = expf(lg[i] - m2); s2 += p[i]; }
    for (int i = 0; i < 10; i++) p[i] /= s2;
    int idx = 0; float best = p[0];
    for (int i = 1; i < 10; i++) if (p[i] > best) { best = p[i]; idx = i; }
    g_index = idx;
    g_w = (1.f - p[idx]) + p[idx];   // straight-through forward value
}

// ---------------------------------------------------------------------------
// Cheap branches: none(0), avg_pool3(1), max_pool3(2), skip(9)
// ---------------------------------------------------------------------------
__global__ void simple_k(const float* __restrict__ x, float* __restrict__ out)
{
    int idx = g_index;
    if (idx >= 3 && idx <= 8) return;
    int i = blockIdx.x * 256 + threadIdx.x;
    if (i >= NTOT) return;
    float xv = x[i];
    float w = g_w;
    float r;
    if (idx == 0) {
        r = xv;                      // w*0 + x
    } else if (idx == 9) {
        r = w * xv + xv;             // skip
    } else {
        int s = (i / H) % S;
        if (idx == 1) {              // avg pool, count_include_pad
            float l = (s > 0)     ? x[i - H] : 0.f;
            float rr = (s < S-1)  ? x[i + H] : 0.f;
            r = w * ((l + xv + rr) * (1.f/3.f)) + xv;
        } else {                     // max pool, -inf pad
            float l = (s > 0)     ? x[i - H] : -FLT_MAX;
            float rr = (s < S-1)  ? x[i + H] : -FLT_MAX;
            r = w * fmaxf(fmaxf(l, xv), rr) + xv;
        }
    }
    out[i] = r;
}

// ---------------------------------------------------------------------------
// Depthwise dilated conv (branches 6,7,8). dilation=2, pad=k-1.
// Writes g_dw[b][c][s].
// ---------------------------------------------------------------------------
__global__ void dw_k(const float* __restrict__ x,
                     const float* __restrict__ wd3,
                     const float* __restrict__ wd5,
                     const float* __restrict__ wd7)
{
    int idx = g_index;
    if (idx < 6 || idx > 8) return;
    int k = 3 + 2 * (idx - 6);
    const float* wd = (idx == 6) ? wd3 : (idx == 7) ? wd5 : wd7;
    int i = blockIdx.x * 256 + threadIdx.x;
    if (i >= NTOT) return;
    int c = i % H;
    int s = (i / H) % S;
    int b = i / (H * S);
    float acc = 0.f;
    for (int t = 0; t < k; t++) {
        int sp = s - (k - 1) + 2 * t;
        if (sp >= 0 && sp < S) {
            float v = x[(b * S + sp) * H + c];
            acc += fmaxf(v, 0.f) * wd[c * k + t];
        }
    }
    g_dw[(b * H + c) * S + s] = acc;
}

// ---------------------------------------------------------------------------
// Unified conv GEMM.
//   nor_conv (idx 3..5):  A[b,c,s'] = relu(x[b,s',c]),  W[o][c][t], pad=k/2
//   dil point (idx 6..8): A[b,c,s'] = g_dw[b][c][s'],   W[o][c],    k=1,pad=0
// Output g_y[b][o][s]. Tile 64 s x 64 o, 16-channel chunks, 4x4 microtile.
// ---------------------------------------------------------------------------
#define TS 64
#define TO 64
#define TC 16

__global__ __launch_bounds__(256) void conv_k(
    const float* __restrict__ x,
    const float* __restrict__ wn3, const float* __restrict__ wn5, const float* __restrict__ wn7,
    const float* __restrict__ wp3, const float* __restrict__ wp5, const float* __restrict__ wp7)
{
    int idx = g_index;
    if (idx < 3 || idx > 8) return;
    bool nor = (idx < 6);
    int k, pad;
    const float* W;
    if (nor) { k = 3 + 2 * (idx - 3); pad = k / 2;
               W = (idx == 3) ? wn3 : (idx == 4) ? wn5 : wn7; }
    else     { k = 1; pad = 0;
               W = (idx == 6) ? wp3 : (idx == 7) ? wp5 : wp7; }

    __shared__ float xs[TC][TS + 8];      // s range: TS + (k-1) <= 70
    __shared__ float ws[7][TC][TO];

    int S0 = blockIdx.x * TS;
    int O0 = blockIdx.y * TO;
    int b  = blockIdx.z;
    int tid = threadIdx.x;
    int ts = tid & 15, to = tid >> 4;

    float acc[4][4];
    #pragma unroll
    for (int i = 0; i < 4; i++)
        #pragma unroll
        for (int j = 0; j < 4; j++) acc[i][j] = 0.f;

    for (int c0 = 0; c0 < H; c0 += TC) {
        // load A tile
        for (int i = tid; i < TC * (TS + 6); i += 256) {
            int c = i & 15;
            int s = i >> 4;
            int sp = S0 + s - pad;
            float v = 0.f;
            if (sp >= 0 && sp < S) {
                if (nor) { v = x[(b * S + sp) * H + (c0 + c)]; v = fmaxf(v, 0.f); }
                else     { v = g_dw[(b * H + (c0 + c)) * S + sp]; }
            }
            xs[c][s] = v;
        }
        // load W tile
        int tot = k * TC * TO;
        for (int i = tid; i < tot; i += 256) {
            int o = i & 63;
            int r = i >> 6;
            int c = r & 15;
            int t = r >> 4;
            float wv;
            if (nor) wv = W[((O0 + o) * H + (c0 + c)) * k + t];
            else     wv = W[(O0 + o) * H + (c0 + c)];
            ws[t][c][o] = wv;
        }
        __syncthreads();

        for (int t = 0; t < k; t++) {
            #pragma unroll
            for (int c = 0; c < TC; c++) {
                float a0 = xs[c][ts * 4 + 0 + t];
                float a1 = xs[c][ts * 4 + 1 + t];
                float a2 = xs[c][ts * 4 + 2 + t];
                float a3 = xs[c][ts * 4 + 3 + t];
                float4 wv = *(const float4*)&ws[t][c][to * 4];
                acc[0][0] += a0 * wv.x; acc[0][1] += a0 * wv.y;
                acc[0][2] += a0 * wv.z; acc[0][3] += a0 * wv.w;
                acc[1][0] += a1 * wv.x; acc[1][1] += a1 * wv.y;
                acc[1][2] += a1 * wv.z; acc[1][3] += a1 * wv.w;
                acc[2][0] += a2 * wv.x; acc[2][1] += a2 * wv.y;
                acc[2][2] += a2 * wv.z; acc[2][3] += a2 * wv.w;
                acc[3][0] += a3 * wv.x; acc[3][1] += a3 * wv.y;
                acc[3][2] += a3 * wv.z; acc[3][3] += a3 * wv.w;
            }
        }
        __syncthreads();
    }

    #pragma unroll
    for (int j = 0; j < 4; j++) {
        int o = O0 + to * 4 + j;
        float4 v = make_float4(acc[0][j], acc[1][j], acc[2][j], acc[3][j]);
        *(float4*)&g_y[(b * H + o) * S + S0 + ts * 4] = v;
    }
}

// ---------------------------------------------------------------------------
// BatchNorm stats (training mode): per-channel mean/var over (B, S) = 4096.
// ---------------------------------------------------------------------------
__global__ void bnstats_k()
{
    int idx = g_index;
    if (idx < 3 || idx > 8) return;
    int o = blockIdx.x;
    int tid = threadIdx.x;
    double s = 0.0, ss = 0.0;
    for (int i = tid; i < B * S; i += 256) {
        int b = i >> 9;
        int si = i & 511;
        float v = g_y[(b * H + o) * S + si];
        s += v;
        ss += (double)v * v;
    }
    __shared__ double rs[256], rss[256];
    rs[tid] = s; rss[tid] = ss;
    __syncthreads();
    for (int off = 128; off > 0; off >>= 1) {
        if (tid < off) { rs[tid] += rs[tid + off]; rss[tid] += rss[tid + off]; }
        __syncthreads();
    }
    if (tid == 0) {
        double mean = rs[0] / (B * S);
        double var = rss[0] / (B * S) - mean * mean;
        g_mean[o] = (float)mean;
        g_var[o]  = (float)var;
    }
}

// ---------------------------------------------------------------------------
// BN apply + gate weight + residual + transpose back to [B,S,H].
// ---------------------------------------------------------------------------
__global__ void finalize_k(const float* __restrict__ x,
                           const float* __restrict__ g3, const float* __restrict__ b3,
                           const float* __restrict__ g5, const float* __restrict__ b5,
                           const float* __restrict__ g7, const float* __restrict__ b7,
                           const float* __restrict__ gd3, const float* __restrict__ bd3,
                           const float* __restrict__ gd5, const float* __restrict__ bd5,
                           const float* __restrict__ gd7, const float* __restrict__ bd7,
                           float* __restrict__ out)
{
    int idx = g_index;
    if (idx < 3 || idx > 8) return;
    const float* gamma; const float* beta;
    switch (idx) {
        case 3: gamma = g3;  beta = b3;  break;
        case 4: gamma = g5;  beta = b5;  break;
        case 5: gamma = g7;  beta = b7;  break;
        case 6: gamma = gd3; beta = bd3; break;
        case 7: gamma = gd5; beta = bd5; break;
        default: gamma = gd7; beta = bd7; break;
    }
    int i = blockIdx.x * 256 + threadIdx.x;
    if (i >= NTOT) return;
    int h = i % H;
    int s = (i / H) % S;
    int b = i / (H * S);
    float y = g_y[(b * H + h) * S + s];
    float bn = (y - g_mean[h]) * rsqrtf(g_var[h] + 1e-5f) * gamma[h] + beta[h];
    out[i] = g_w * bn + x[i];
}

// ---------------------------------------------------------------------------
extern "C" void kernel_launch(void* const* d_in, const int* in_sizes, int n_in,
                              void* d_out, int out_size)
{
    const float* x    = (const float*)d_in[0];
    const float* u    = (const float*)d_in[1];
    const float* arch = (const float*)d_in[2];
    const float* wn3 = (const float*)d_in[3];
    const float* gn3 = (const float*)d_in[4];
    const float* bn3 = (const float*)d_in[5];
    const float* wn5 = (const float*)d_in[6];
    const float* gn5 = (const float*)d_in[7];
    const float* bn5 = (const float*)d_in[8];
    const float* wn7 = (const float*)d_in[9];
    const float* gn7 = (const float*)d_in[10];
    const float* bn7 = (const float*)d_in[11];
    const float* wd3 = (const float*)d_in[12];
    const float* wp3 = (const float*)d_in[13];
    const float* gd3 = (const float*)d_in[14];
    const float* bd3 = (const float*)d_in[15];
    const float* wd5 = (const float*)d_in[16];
    const float* wp5 = (const float*)d_in[17];
    const float* gd5 = (const float*)d_in[18];
    const float* bd5 = (const float*)d_in[19];
    const float* wd7 = (const float*)d_in[20];
    const float* wp7 = (const float*)d_in[21];
    const float* gd7 = (const float*)d_in[22];
    const float* bd7 = (const float*)d_in[23];
    float* out = (float*)d_out;

    gate_k<<<1, 32>>>(u, arch);

    int nb = (NTOT + 255) / 256;
    simple_k<<<nb, 256>>>(x, out);
    dw_k<<<nb, 256>>>(x, wd3, wd5, wd7);
    dim3 cg(S / TS, H / TO, B);
    conv_k<<<cg, 256>>>(x, wn3, wn5, wn7, wp3, wp5, wp7);
    bnstats_k<<<H, 256>>>();
    finalize_k<<<nb, 256>>>(x, gn3, bn3, gn5, bn5, gn7, bn7,
                            gd3, bd3, gd5, bd5, gd7, bd7, out);
}

// round 5
// speedup vs baseline: 2.6266x; 2.6266x over previous
#include <cuda_runtime.h>
#include <math.h>
#include <float.h>

#define B 8
#define S 512
#define H 768
#define NTOT (B*S*H)       // 3145728
#define NT4  (NTOT/4)      // 786432
#define TS 64
#define TO 64
#define TC 16
#define NTILE 64           // (S/TS) * B

// scratch (no cudaMalloc allowed)
__device__ int   g_index_d;
__device__ float g_w_d;
__device__ __align__(16) float g_y[NTOT];        // conv output [B][O][S]
__device__ float g_psum [NTILE * H];
__device__ float g_pssum[NTILE * H];
__device__ float g_scale[H];                     // gamma * rsqrt(var+eps)
__device__ float g_shift[H];                     // beta - mean*scale

// ---------------------------------------------------------------------------
// Gumbel straight-through gate, computed inline (tiny).
// ---------------------------------------------------------------------------
__device__ __forceinline__ void compute_gate(const float* __restrict__ u,
                                             const float* __restrict__ arch,
                                             int& idx_out, float& w_out)
{
    float a[10], lg[10], p[10];
    float m = -FLT_MAX;
    #pragma unroll
    for (int i = 0; i < 10; i++) { a[i] = arch[i]; m = fmaxf(m, a[i]); }
    float se = 0.f;
    #pragma unroll
    for (int i = 0; i < 10; i++) se += expf(a[i] - m);
    float lse = m + logf(se);
    float m2 = -FLT_MAX;
    #pragma unroll
    for (int i = 0; i < 10; i++) {
        float uc  = fminf(fmaxf(u[i], 1e-9f), 1.f - 1e-9f);
        float gum = -logf(-logf(uc));
        lg[i] = ((a[i] - lse) + gum) * 0.1f;      // /TEM, TEM=10
        m2 = fmaxf(m2, lg[i]);
    }
    float s2 = 0.f;
    #pragma unroll
    for (int i = 0; i < 10; i++) { p[i] = expf(lg[i] - m2); s2 += p[i]; }
    int idx = 0; float best = p[0];
    #pragma unroll
    for (int i = 1; i < 10; i++) if (p[i] > best) { best = p[i]; idx = i; }
    float pi = best / s2;
    idx_out = idx;
    w_out = (1.f - pi) + pi;                       // straight-through fwd value
}

// ---------------------------------------------------------------------------
// main_k: gate inline; cheap branches (0,1,2,9) do vectorized elementwise;
// heavy branches (3..8) do tiled implicit-GEMM conv with inline depthwise and
// per-tile BN partial sums in the epilogue.
// grid = (S/TS=8, H/TO=12, B=8), 256 threads.
// ---------------------------------------------------------------------------
__global__ __launch_bounds__(256) void main_k(
    const float* __restrict__ x,
    const float* __restrict__ u,   const float* __restrict__ arch,
    const float* __restrict__ wn3, const float* __restrict__ wn5, const float* __restrict__ wn7,
    const float* __restrict__ wd3, const float* __restrict__ wd5, const float* __restrict__ wd7,
    const float* __restrict__ wp3, const float* __restrict__ wp5, const float* __restrict__ wp7,
    float* __restrict__ out)
{
    __shared__ int   s_idx;
    __shared__ float s_w;
    int tid = threadIdx.x;
    if (tid == 0) {
        int ii; float ww;
        compute_gate(u, arch, ii, ww);
        s_idx = ii; s_w = ww;
        if (blockIdx.x == 0 && blockIdx.y == 0 && blockIdx.z == 0) {
            g_index_d = ii; g_w_d = ww;
        }
    }
    __syncthreads();
    int idx = s_idx;
    float w = s_w;

    if (idx < 3 || idx > 8) {
        // ---------------- cheap path: float4 elementwise ----------------
        int bid = (blockIdx.z * 12 + blockIdx.y) * 8 + blockIdx.x;   // 0..767
        const float4* x4 = (const float4*)x;
        float4* o4 = (float4*)out;
        #pragma unroll
        for (int it = 0; it < 4; it++) {
            int i4 = bid * 1024 + it * 256 + tid;                    // < NT4
            float4 xv = x4[i4];
            float4 r;
            if (idx == 0) {
                r = xv;
            } else if (idx == 9) {
                r.x = fmaf(w, xv.x, xv.x); r.y = fmaf(w, xv.y, xv.y);
                r.z = fmaf(w, xv.z, xv.z); r.w = fmaf(w, xv.w, xv.w);
            } else {
                int s = (i4 / (H / 4)) % S;
                float pad = (idx == 1) ? 0.f : -INFINITY;
                float4 l  = make_float4(pad, pad, pad, pad);
                float4 rr = l;
                if (s > 0)     l  = x4[i4 - H / 4];
                if (s < S - 1) rr = x4[i4 + H / 4];
                if (idx == 1) {
                    r.x = fmaf(w, (l.x + xv.x + rr.x) * (1.f / 3.f), xv.x);
                    r.y = fmaf(w, (l.y + xv.y + rr.y) * (1.f / 3.f), xv.y);
                    r.z = fmaf(w, (l.z + xv.z + rr.z) * (1.f / 3.f), xv.z);
                    r.w = fmaf(w, (l.w + xv.w + rr.w) * (1.f / 3.f), xv.w);
                } else {
                    r.x = fmaf(w, fmaxf(fmaxf(l.x, xv.x), rr.x), xv.x);
                    r.y = fmaf(w, fmaxf(fmaxf(l.y, xv.y), rr.y), xv.y);
                    r.z = fmaf(w, fmaxf(fmaxf(l.z, xv.z), rr.z), xv.z);
                    r.w = fmaf(w, fmaxf(fmaxf(l.w, xv.w), rr.w), xv.w);
                }
            }
            o4[i4] = r;
        }
        return;
    }

    // ---------------- heavy path: tiled conv GEMM ----------------
    bool nor = (idx < 6);
    int k, pad_;
    const float* W;
    int kd = 0; const float* wd = nullptr;
    if (nor) {
        k = 3 + 2 * (idx - 3); pad_ = k / 2;
        W = (idx == 3) ? wn3 : (idx == 4) ? wn5 : wn7;
    } else {
        k = 1; pad_ = 0;
        W = (idx == 6) ? wp3 : (idx == 7) ? wp5 : wp7;
        kd = 3 + 2 * (idx - 6);
        wd = (idx == 6) ? wd3 : (idx == 7) ? wd5 : wd7;
    }

    __shared__ float xs[TC][TS + 8];
    __shared__ float ws[7][TC][TO];

    int S0 = blockIdx.x * TS;
    int O0 = blockIdx.y * TO;
    int b  = blockIdx.z;
    int ts = tid & 15, to = tid >> 4;

    float acc[4][4];
    #pragma unroll
    for (int i = 0; i < 4; i++)
        #pragma unroll
        for (int j = 0; j < 4; j++) acc[i][j] = 0.f;

    for (int c0 = 0; c0 < H; c0 += TC) {
        // A tile (inline depthwise for dil branches)
        for (int i = tid; i < TC * (TS + 6); i += 256) {
            int c = i & 15;
            int s = i >> 4;
            int sp = S0 + s - pad_;
            float v = 0.f;
            if (sp >= 0 && sp < S) {
                if (nor) {
                    v = fmaxf(x[(b * S + sp) * H + (c0 + c)], 0.f);
                } else {
                    float a2 = 0.f;
                    for (int t = 0; t < kd; t++) {
                        int spp = sp - (kd - 1) + 2 * t;
                        if (spp >= 0 && spp < S)
                            a2 += fmaxf(x[(b * S + spp) * H + (c0 + c)], 0.f)
                                  * wd[(c0 + c) * kd + t];
                    }
                    v = a2;
                }
            }
            xs[c][s] = v;
        }
        // W tile
        int tot = k * TC * TO;
        for (int i = tid; i < tot; i += 256) {
            int o = i & 63;
            int r = i >> 6;
            int c = r & 15;
            int t = r >> 4;
            float wv = nor ? W[((O0 + o) * H + (c0 + c)) * k + t]
                           : W[(O0 + o) * H + (c0 + c)];
            ws[t][c][o] = wv;
        }
        __syncthreads();

        for (int t = 0; t < k; t++) {
            #pragma unroll
            for (int c = 0; c < TC; c++) {
                float a0 = xs[c][ts * 4 + 0 + t];
                float a1 = xs[c][ts * 4 + 1 + t];
                float a2 = xs[c][ts * 4 + 2 + t];
                float a3 = xs[c][ts * 4 + 3 + t];
                float4 wv = *(const float4*)&ws[t][c][to * 4];
                acc[0][0] += a0 * wv.x; acc[0][1] += a0 * wv.y;
                acc[0][2] += a0 * wv.z; acc[0][3] += a0 * wv.w;
                acc[1][0] += a1 * wv.x; acc[1][1] += a1 * wv.y;
                acc[1][2] += a1 * wv.z; acc[1][3] += a1 * wv.w;
                acc[2][0] += a2 * wv.x; acc[2][1] += a2 * wv.y;
                acc[2][2] += a2 * wv.z; acc[2][3] += a2 * wv.w;
                acc[3][0] += a3 * wv.x; acc[3][1] += a3 * wv.y;
                acc[3][2] += a3 * wv.z; acc[3][3] += a3 * wv.w;
            }
        }
        __syncthreads();
    }

    // write y tile
    #pragma unroll
    for (int j = 0; j < 4; j++) {
        int o = O0 + to * 4 + j;
        float4 v = make_float4(acc[0][j], acc[1][j], acc[2][j], acc[3][j]);
        *(float4*)&g_y[(b * H + o) * S + S0 + ts * 4] = v;
    }

    // BN partial sums per (tile, channel) — deterministic, no atomics
    int tile = blockIdx.z * 8 + blockIdx.x;   // 0..63
    #pragma unroll
    for (int j = 0; j < 4; j++) {
        float ps  = acc[0][j] + acc[1][j] + acc[2][j] + acc[3][j];
        float pss = acc[0][j]*acc[0][j] + acc[1][j]*acc[1][j]
                  + acc[2][j]*acc[2][j] + acc[3][j]*acc[3][j];
        #pragma unroll
        for (int off = 8; off > 0; off >>= 1) {
            ps  += __shfl_down_sync(0xffffffffu, ps,  off, 16);
            pss += __shfl_down_sync(0xffffffffu, pss, off, 16);
        }
        if (ts == 0) {
            int o = O0 + to * 4 + j;
            g_psum [tile * H + o] = ps;
            g_pssum[tile * H + o] = pss;
        }
    }
}

// ---------------------------------------------------------------------------
// stats_k: per-channel mean/var from 64 tile partials; folds gamma/beta into
// scale/shift. Heavy-only (early exit otherwise). grid = H, 32 threads.
// ---------------------------------------------------------------------------
__global__ void stats_k(const float* __restrict__ g3,  const float* __restrict__ b3,
                        const float* __restrict__ g5,  const float* __restrict__ b5,
                        const float* __restrict__ g7,  const float* __restrict__ b7,
                        const float* __restrict__ gd3, const float* __restrict__ bd3,
                        const float* __restrict__ gd5, const float* __restrict__ bd5,
                        const float* __restrict__ gd7, const float* __restrict__ bd7)
{
    int idx = g_index_d;
    if (idx < 3 || idx > 8) return;
    int o = blockIdx.x;
    int t = threadIdx.x;
    float s1 = g_psum [t * H + o] + g_psum [(t + 32) * H + o];
    float s2 = g_pssum[t * H + o] + g_pssum[(t + 32) * H + o];
    #pragma unroll
    for (int off = 16; off > 0; off >>= 1) {
        s1 += __shfl_down_sync(0xffffffffu, s1, off);
        s2 += __shfl_down_sync(0xffffffffu, s2, off);
    }
    if (t == 0) {
        const float* gamma; const float* beta;
        switch (idx) {
            case 3: gamma = g3;  beta = b3;  break;
            case 4: gamma = g5;  beta = b5;  break;
            case 5: gamma = g7;  beta = b7;  break;
            case 6: gamma = gd3; beta = bd3; break;
            case 7: gamma = gd5; beta = bd5; break;
            default: gamma = gd7; beta = bd7; break;
        }
        float mean = s1 * (1.f / 4096.f);
        float var  = s2 * (1.f / 4096.f) - mean * mean;
        float sc = rsqrtf(var + 1e-5f) * gamma[o];
        g_scale[o] = sc;
        g_shift[o] = beta[o] - mean * sc;
    }
}

// ---------------------------------------------------------------------------
// finalize_k: BN apply + gate weight + residual + transpose. Heavy-only.
// grid = 768 blocks * 256 threads * 16 elems.
// ---------------------------------------------------------------------------
__global__ __launch_bounds__(256) void finalize_k(const float* __restrict__ x,
                                                  float* __restrict__ out)
{
    int idx = g_index_d;
    if (idx < 3 || idx > 8) return;
    float w = g_w_d;
    int bid = blockIdx.x;
    for (int it = 0; it < 16; it++) {
        int i = (bid * 16 + it) * 256 + threadIdx.x;
        int h = i % H;
        int s = (i / H) % S;
        int b = i / (H * S);
        float y  = g_y[(b * H + h) * S + s];
        float bn = fmaf(y, g_scale[h], g_shift[h]);
        out[i] = fmaf(w, bn, x[i]);
    }
}

// ---------------------------------------------------------------------------
extern "C" void kernel_launch(void* const* d_in, const int* in_sizes, int n_in,
                              void* d_out, int out_size)
{
    const float* x    = (const float*)d_in[0];
    const float* u    = (const float*)d_in[1];
    const float* arch = (const float*)d_in[2];
    const float* wn3 = (const float*)d_in[3];
    const float* gn3 = (const float*)d_in[4];
    const float* bn3 = (const float*)d_in[5];
    const float* wn5 = (const float*)d_in[6];
    const float* gn5 = (const float*)d_in[7];
    const float* bn5 = (const float*)d_in[8];
    const float* wn7 = (const float*)d_in[9];
    const float* gn7 = (const float*)d_in[10];
    const float* bn7 = (const float*)d_in[11];
    const float* wd3 = (const float*)d_in[12];
    const float* wp3 = (const float*)d_in[13];
    const float* gd3 = (const float*)d_in[14];
    const float* bd3 = (const float*)d_in[15];
    const float* wd5 = (const float*)d_in[16];
    const float* wp5 = (const float*)d_in[17];
    const float* gd5 = (const float*)d_in[18];
    const float* bd5 = (const float*)d_in[19];
    const float* wd7 = (const float*)d_in[20];
    const float* wp7 = (const float*)d_in[21];
    const float* gd7 = (const float*)d_in[22];
    const float* bd7 = (const float*)d_in[23];
    float* out = (float*)d_out;

    dim3 cg(S / TS, H / TO, B);   // (8, 12, 8) = 768 blocks
    main_k<<<cg, 256>>>(x, u, arch,
                        wn3, wn5, wn7,
                        wd3, wd5, wd7,
                        wp3, wp5, wp7,
                        out);
    stats_k<<<H, 32>>>(gn3, bn3, gn5, bn5, gn7, bn7,
                       gd3, bd3, gd5, bd5, gd7, bd7);
    finalize_k<<<768, 256>>>(x, out);
}

// round 6
// speedup vs baseline: 3.9697x; 1.5114x over previous
#include <cuda_runtime.h>
#include <math.h>
#include <float.h>

#define B 8
#define S 512
#define H 768
#define NTOT (B*S*H)       // 3145728
#define NT4  (NTOT/4)      // 786432
#define GRID 512
#define STRIDE4 (GRID*256) // 131072 ; NT4 / STRIDE4 = 6 exactly
#define TS 64
#define TO 64
#define TC 16
#define NTILE 64           // (S/TS) * B

// scratch (no cudaMalloc allowed)
__device__ __align__(16) float g_y[NTOT];        // conv output [B][O][S]
__device__ float g_psum [NTILE * H];
__device__ float g_pssum[NTILE * H];
__device__ float g_scale[H];
__device__ float g_shift[H];
__device__ unsigned g_ctr   = 0;                 // last-block ticket
__device__ unsigned g_epoch = 0;                 // stats-done epoch

// ---------------------------------------------------------------------------
// Gumbel straight-through gate (fast math).
// ---------------------------------------------------------------------------
__device__ __forceinline__ void compute_gate(const float* __restrict__ u,
                                             const float* __restrict__ arch,
                                             int& idx_out, float& w_out)
{
    float a[10], lg[10], p[10];
    float m = -FLT_MAX;
    #pragma unroll
    for (int i = 0; i < 10; i++) { a[i] = arch[i]; m = fmaxf(m, a[i]); }
    float se = 0.f;
    #pragma unroll
    for (int i = 0; i < 10; i++) se += __expf(a[i] - m);
    float lse = m + __logf(se);
    float m2 = -FLT_MAX;
    #pragma unroll
    for (int i = 0; i < 10; i++) {
        float uc  = fminf(fmaxf(u[i], 1e-9f), 1.f - 1e-9f);
        float gum = -__logf(-__logf(uc));
        lg[i] = ((a[i] - lse) + gum) * 0.1f;      // /TEM, TEM=10
        m2 = fmaxf(m2, lg[i]);
    }
    float s2 = 0.f;
    #pragma unroll
    for (int i = 0; i < 10; i++) { p[i] = __expf(lg[i] - m2); s2 += p[i]; }
    int idx = 0; float best = p[0];
    #pragma unroll
    for (int i = 1; i < 10; i++) if (p[i] > best) { best = p[i]; idx = i; }
    float pi = best / s2;
    idx_out = idx;
    w_out = (1.f - pi) + pi;                       // straight-through fwd value
}

// ---------------------------------------------------------------------------
// Single persistent kernel. grid = 512 blocks x 256 threads.
// Cheap branches (0,1,2,9): vectorized elementwise, 6 float4/thread, batched.
// Heavy branches (3..8): each block does 1-2 conv tiles, then a chip-wide
// last-block reduction computes BN scale/shift, then all blocks finalize.
// All 512 blocks are simultaneously resident (launch_bounds(256,4): 4/SM x
// 148 SMs = 592 >= 512), so the epoch spin cannot deadlock.
// ---------------------------------------------------------------------------
__global__ __launch_bounds__(256, 4) void main_k(
    const float* __restrict__ x,
    const float* __restrict__ u,   const float* __restrict__ arch,
    const float* __restrict__ wn3, const float* __restrict__ wn5, const float* __restrict__ wn7,
    const float* __restrict__ wd3, const float* __restrict__ wd5, const float* __restrict__ wd7,
    const float* __restrict__ wp3, const float* __restrict__ wp5, const float* __restrict__ wp7,
    const float* __restrict__ g3,  const float* __restrict__ b3,
    const float* __restrict__ g5,  const float* __restrict__ b5,
    const float* __restrict__ g7,  const float* __restrict__ b7,
    const float* __restrict__ gd3, const float* __restrict__ bd3,
    const float* __restrict__ gd5, const float* __restrict__ bd5,
    const float* __restrict__ gd7, const float* __restrict__ bd7,
    float* __restrict__ out)
{
    __shared__ int      s_idx;
    __shared__ float    s_w;
    __shared__ unsigned s_epoch;
    __shared__ int      s_last;
    int tid = threadIdx.x;
    int bid = blockIdx.x;
    if (tid == 0) {
        int ii; float ww;
        compute_gate(u, arch, ii, ww);
        s_idx = ii; s_w = ww;
        s_epoch = *(volatile unsigned*)&g_epoch;   // capture before any ticket
    }
    __syncthreads();
    int idx = s_idx;
    float w = s_w;
    int base = bid * 256 + tid;

    if (idx < 3 || idx > 8) {
        // ---------------- cheap path ----------------
        const float4* x4 = (const float4*)x;
        float4* o4 = (float4*)out;
        if (idx == 0 || idx == 9) {
            float4 v[6];
            #pragma unroll
            for (int j = 0; j < 6; j++) v[j] = x4[base + j * STRIDE4];
            if (idx == 0) {
                #pragma unroll
                for (int j = 0; j < 6; j++) o4[base + j * STRIDE4] = v[j];
            } else {
                #pragma unroll
                for (int j = 0; j < 6; j++) {
                    float4 r;
                    r.x = fmaf(w, v[j].x, v[j].x); r.y = fmaf(w, v[j].y, v[j].y);
                    r.z = fmaf(w, v[j].z, v[j].z); r.w = fmaf(w, v[j].w, v[j].w);
                    o4[base + j * STRIDE4] = r;
                }
            }
        } else {
            float pad = (idx == 1) ? 0.f : -INFINITY;
            #pragma unroll
            for (int j = 0; j < 6; j++) {
                int i4 = base + j * STRIDE4;
                int s = (i4 / (H / 4)) % S;
                float4 xv = x4[i4];
                float4 l  = make_float4(pad, pad, pad, pad);
                float4 rr = l;
                if (s > 0)     l  = x4[i4 - H / 4];
                if (s < S - 1) rr = x4[i4 + H / 4];
                float4 r;
                if (idx == 1) {
                    r.x = fmaf(w, (l.x + xv.x + rr.x) * (1.f / 3.f), xv.x);
                    r.y = fmaf(w, (l.y + xv.y + rr.y) * (1.f / 3.f), xv.y);
                    r.z = fmaf(w, (l.z + xv.z + rr.z) * (1.f / 3.f), xv.z);
                    r.w = fmaf(w, (l.w + xv.w + rr.w) * (1.f / 3.f), xv.w);
                } else {
                    r.x = fmaf(w, fmaxf(fmaxf(l.x, xv.x), rr.x), xv.x);
                    r.y = fmaf(w, fmaxf(fmaxf(l.y, xv.y), rr.y), xv.y);
                    r.z = fmaf(w, fmaxf(fmaxf(l.z, xv.z), rr.z), xv.z);
                    r.w = fmaf(w, fmaxf(fmaxf(l.w, xv.w), rr.w), xv.w);
                }
                o4[i4] = r;
            }
        }
        return;
    }

    // ---------------- heavy path: tiled conv GEMM ----------------
    bool nor = (idx < 6);
    int k, pad_;
    const float* W;
    int kd = 0; const float* wd = nullptr;
    if (nor) {
        k = 3 + 2 * (idx - 3); pad_ = k / 2;
        W = (idx == 3) ? wn3 : (idx == 4) ? wn5 : wn7;
    } else {
        k = 1; pad_ = 0;
        W = (idx == 6) ? wp3 : (idx == 7) ? wp5 : wp7;
        kd = 3 + 2 * (idx - 6);
        wd = (idx == 6) ? wd3 : (idx == 7) ? wd5 : wd7;
    }

    __shared__ float xs[TC][TS + 8];
    __shared__ float ws[7][TC][TO];
    int ts = tid & 15, to = tid >> 4;

    for (int tt = bid; tt < 768; tt += GRID) {
        int tx = tt & 7;
        int ty = (tt >> 3) % 12;
        int b  = tt / 96;
        int S0 = tx * TS;
        int O0 = ty * TO;

        float acc[4][4];
        #pragma unroll
        for (int i = 0; i < 4; i++)
            #pragma unroll
            for (int j = 0; j < 4; j++) acc[i][j] = 0.f;

        for (int c0 = 0; c0 < H; c0 += TC) {
            // A tile (inline depthwise for dil branches)
            for (int i = tid; i < TC * (TS + 6); i += 256) {
                int c = i & 15;
                int s = i >> 4;
                int sp = S0 + s - pad_;
                float v = 0.f;
                if (sp >= 0 && sp < S) {
                    if (nor) {
                        v = fmaxf(x[(b * S + sp) * H + (c0 + c)], 0.f);
                    } else {
                        float a2 = 0.f;
                        for (int t = 0; t < kd; t++) {
                            int spp = sp - (kd - 1) + 2 * t;
                            if (spp >= 0 && spp < S)
                                a2 += fmaxf(x[(b * S + spp) * H + (c0 + c)], 0.f)
                                      * wd[(c0 + c) * kd + t];
                        }
                        v = a2;
                    }
                }
                xs[c][s] = v;
            }
            // W tile
            int tot = k * TC * TO;
            for (int i = tid; i < tot; i += 256) {
                int o = i & 63;
                int r = i >> 6;
                int c = r & 15;
                int t = r >> 4;
                float wv = nor ? W[((O0 + o) * H + (c0 + c)) * k + t]
                               : W[(O0 + o) * H + (c0 + c)];
                ws[t][c][o] = wv;
            }
            __syncthreads();

            for (int t = 0; t < k; t++) {
                #pragma unroll
                for (int c = 0; c < TC; c++) {
                    float a0 = xs[c][ts * 4 + 0 + t];
                    float a1 = xs[c][ts * 4 + 1 + t];
                    float a2 = xs[c][ts * 4 + 2 + t];
                    float a3 = xs[c][ts * 4 + 3 + t];
                    float4 wv = *(const float4*)&ws[t][c][to * 4];
                    acc[0][0] += a0 * wv.x; acc[0][1] += a0 * wv.y;
                    acc[0][2] += a0 * wv.z; acc[0][3] += a0 * wv.w;
                    acc[1][0] += a1 * wv.x; acc[1][1] += a1 * wv.y;
                    acc[1][2] += a1 * wv.z; acc[1][3] += a1 * wv.w;
                    acc[2][0] += a2 * wv.x; acc[2][1] += a2 * wv.y;
                    acc[2][2] += a2 * wv.z; acc[2][3] += a2 * wv.w;
                    acc[3][0] += a3 * wv.x; acc[3][1] += a3 * wv.y;
                    acc[3][2] += a3 * wv.z; acc[3][3] += a3 * wv.w;
                }
            }
            __syncthreads();
        }

        // write y tile + BN partial sums (deterministic, no atomics)
        int tile = b * 8 + tx;                 // 0..63
        #pragma unroll
        for (int j = 0; j < 4; j++) {
            int o = O0 + to * 4 + j;
            float4 v = make_float4(acc[0][j], acc[1][j], acc[2][j], acc[3][j]);
            *(float4*)&g_y[(b * H + o) * S + S0 + ts * 4] = v;

            float ps  = acc[0][j] + acc[1][j] + acc[2][j] + acc[3][j];
            float pss = acc[0][j]*acc[0][j] + acc[1][j]*acc[1][j]
                      + acc[2][j]*acc[2][j] + acc[3][j]*acc[3][j];
            #pragma unroll
            for (int off = 8; off > 0; off >>= 1) {
                ps  += __shfl_down_sync(0xffffffffu, ps,  off, 16);
                pss += __shfl_down_sync(0xffffffffu, pss, off, 16);
            }
            if (ts == 0) {
                g_psum [tile * H + o] = ps;
                g_pssum[tile * H + o] = pss;
            }
        }
        __syncthreads();
    }

    // ----- chip-wide: last block computes BN scale/shift -----
    __threadfence();
    if (tid == 0) {
        unsigned t = atomicAdd(&g_ctr, 1u);
        s_last = (t == GRID - 1);
    }
    __syncthreads();

    if (s_last) {
        const float* gamma; const float* beta;
        switch (idx) {
            case 3: gamma = g3;  beta = b3;  break;
            case 4: gamma = g5;  beta = b5;  break;
            case 5: gamma = g7;  beta = b7;  break;
            case 6: gamma = gd3; beta = bd3; break;
            case 7: gamma = gd5; beta = bd5; break;
            default: gamma = gd7; beta = bd7; break;
        }
        #pragma unroll
        for (int q = 0; q < 3; q++) {
            int o = tid + q * 256;
            float s1 = 0.f, s2 = 0.f;
            for (int t = 0; t < NTILE; t++) {
                s1 += g_psum [t * H + o];
                s2 += g_pssum[t * H + o];
            }
            float mean = s1 * (1.f / 4096.f);
            float var  = s2 * (1.f / 4096.f) - mean * mean;
            float sc = rsqrtf(var + 1e-5f) * gamma[o];
            g_scale[o] = sc;
            g_shift[o] = beta[o] - mean * sc;
        }
        __syncthreads();
        __threadfence();
        if (tid == 0) {
            g_ctr = 0;                         // reset for next replay
            __threadfence();
            atomicAdd(&g_epoch, 1u);           // release
        }
    } else {
        if (tid == 0) {
            unsigned old = s_epoch;
            while (*(volatile unsigned*)&g_epoch == old) { __nanosleep(64); }
        }
        __syncthreads();
        __threadfence();
    }

    // ----- finalize: BN apply + gate weight + residual + transpose -----
    const float4* x4 = (const float4*)x;
    float4* o4 = (float4*)out;
    #pragma unroll
    for (int j = 0; j < 6; j++) {
        int i4 = base + j * STRIDE4;
        int h = (i4 % (H / 4)) * 4;
        int s = (i4 / (H / 4)) % S;
        int b2 = i4 / ((H / 4) * S);
        float4 xv = x4[i4];
        float4 r;
        r.x = fmaf(w, fmaf(g_y[(b2 * H + h + 0) * S + s], g_scale[h + 0], g_shift[h + 0]), xv.x);
        r.y = fmaf(w, fmaf(g_y[(b2 * H + h + 1) * S + s], g_scale[h + 1], g_shift[h + 1]), xv.y);
        r.z = fmaf(w, fmaf(g_y[(b2 * H + h + 2) * S + s], g_scale[h + 2], g_shift[h + 2]), xv.z);
        r.w = fmaf(w, fmaf(g_y[(b2 * H + h + 3) * S + s], g_scale[h + 3], g_shift[h + 3]), xv.w);
        o4[i4] = r;
    }
}

// ---------------------------------------------------------------------------
extern "C" void kernel_launch(void* const* d_in, const int* in_sizes, int n_in,
                              void* d_out, int out_size)
{
    const float* x    = (const float*)d_in[0];
    const float* u    = (const float*)d_in[1];
    const float* arch = (const float*)d_in[2];
    const float* wn3 = (const float*)d_in[3];
    const float* gn3 = (const float*)d_in[4];
    const float* bn3 = (const float*)d_in[5];
    const float* wn5 = (const float*)d_in[6];
    const float* gn5 = (const float*)d_in[7];
    const float* bn5 = (const float*)d_in[8];
    const float* wn7 = (const float*)d_in[9];
    const float* gn7 = (const float*)d_in[10];
    const float* bn7 = (const float*)d_in[11];
    const float* wd3 = (const float*)d_in[12];
    const float* wp3 = (const float*)d_in[13];
    const float* gd3 = (const float*)d_in[14];
    const float* bd3 = (const float*)d_in[15];
    const float* wd5 = (const float*)d_in[16];
    const float* wp5 = (const float*)d_in[17];
    const float* gd5 = (const float*)d_in[18];
    const float* bd5 = (const float*)d_in[19];
    const float* wd7 = (const float*)d_in[20];
    const float* wp7 = (const float*)d_in[21];
    const float* gd7 = (const float*)d_in[22];
    const float* bd7 = (const float*)d_in[23];
    float* out = (float*)d_out;

    main_k<<<GRID, 256>>>(x, u, arch,
                          wn3, wn5, wn7,
                          wd3, wd5, wd7,
                          wp3, wp5, wp7,
                          gn3, bn3, gn5, bn5, gn7, bn7,
                          gd3, bd3, gd5, bd5, gd7, bd7,
                          out);
}